// round 13
// baseline (speedup 1.0000x reference)
#include <cuda_runtime.h>
#include <cuda_bf16.h>
#include <cstdint>

// Problem constants (asserted implicitly by scratch sizing)
#define MAX_N 50000
#define MAX_E 800000
#define DF    128   // feature dim / layer width
#define HID   256   // MLP hidden

// ---------------- device scratch (static __device__, no allocs) ----------
__device__ int   g_deg[MAX_N];
__device__ int   g_row_ptr[MAX_N + 1];
__device__ int   g_cursor[MAX_N];
__device__ float g_inv_deg[MAX_N];
__device__ int   g_cols[MAX_E];

__device__ float g_hA[(size_t)MAX_N * DF];
__device__ float g_hB[(size_t)MAX_N * DF];
__device__ float g_nbr[(size_t)MAX_N * DF];
__device__ float g_hidden[(size_t)MAX_N * HID];

// ---------------- CSR build --------------------------------------------
__global__ void k_zero_deg(int n) {
    int i = blockIdx.x * blockDim.x + threadIdx.x;
    if (i < n) g_deg[i] = 0;
}

__global__ void k_hist(const int* __restrict__ ei, int E) {
    int e = blockIdx.x * blockDim.x + threadIdx.x;
    if (e < E) atomicAdd(&g_deg[ei[e]], 1);
}

// single-block exclusive scan over g_deg -> g_row_ptr / g_cursor / g_inv_deg
__global__ void k_scan(int n) {
    __shared__ int sdata[1024];
    __shared__ int s_off;
    if (threadIdx.x == 0) s_off = 0;
    __syncthreads();
    for (int base = 0; base < n; base += 1024) {
        int i = base + (int)threadIdx.x;
        int v = (i < n) ? g_deg[i] : 0;
        sdata[threadIdx.x] = v;
        __syncthreads();
        #pragma unroll
        for (int ofs = 1; ofs < 1024; ofs <<= 1) {
            int t = 0;
            if ((int)threadIdx.x >= ofs) t = sdata[threadIdx.x - ofs];
            __syncthreads();
            sdata[threadIdx.x] += t;
            __syncthreads();
        }
        int excl = s_off + sdata[threadIdx.x] - v;
        if (i < n) {
            g_row_ptr[i] = excl;
            g_cursor[i]  = excl;
            g_inv_deg[i] = 1.0f / fmaxf((float)v, 1.0f);
        }
        __syncthreads();
        if (threadIdx.x == 0) s_off += sdata[1023];
        __syncthreads();
    }
    if (threadIdx.x == 0) g_row_ptr[n] = s_off;
}

__global__ void k_scatter(const int* __restrict__ ei, int E) {
    int e = blockIdx.x * blockDim.x + threadIdx.x;
    if (e < E) {
        int r = ei[e];
        int c = ei[E + e];
        int pos = atomicAdd(&g_cursor[r], 1);
        g_cols[pos] = c;
    }
}

// ---------------- mean-neighbor aggregation (warp per node) -------------
__global__ void k_agg(const float* __restrict__ h, float* __restrict__ outp, int n) {
    int warp = (blockIdx.x * blockDim.x + threadIdx.x) >> 5;
    int lane = threadIdx.x & 31;
    if (warp >= n) return;
    int s = g_row_ptr[warp];
    int e = g_row_ptr[warp + 1];

    float4 acc0 = make_float4(0.f, 0.f, 0.f, 0.f);
    float4 acc1 = make_float4(0.f, 0.f, 0.f, 0.f);
    int j = s;
    for (; j + 1 < e; j += 2) {
        int c0 = g_cols[j];
        int c1 = g_cols[j + 1];
        float4 v0 = ((const float4*)(h + (size_t)c0 * DF))[lane];
        float4 v1 = ((const float4*)(h + (size_t)c1 * DF))[lane];
        acc0.x += v0.x; acc0.y += v0.y; acc0.z += v0.z; acc0.w += v0.w;
        acc1.x += v1.x; acc1.y += v1.y; acc1.z += v1.z; acc1.w += v1.w;
    }
    if (j < e) {
        int c0 = g_cols[j];
        float4 v0 = ((const float4*)(h + (size_t)c0 * DF))[lane];
        acc0.x += v0.x; acc0.y += v0.y; acc0.z += v0.z; acc0.w += v0.w;
    }
    float sc = g_inv_deg[warp];
    float4 r;
    r.x = (acc0.x + acc1.x) * sc;
    r.y = (acc0.y + acc1.y) * sc;
    r.z = (acc0.z + acc1.z) * sc;
    r.w = (acc0.w + acc1.w) * sc;
    ((float4*)(outp + (size_t)warp * DF))[lane] = r;
}

// ---------------- tiled fp32 GEMM: C = [relu](A @ W + bias) -------------
// A: [N,K] lda; W: [K,M] ldw; C: [N,*] ldc (caller pre-offsets C/bias cols)
__global__ __launch_bounds__(256, 4)
void k_gemm(const float* __restrict__ A, int lda,
            const float* __restrict__ W, int ldw,
            const float* __restrict__ bias,
            float* __restrict__ C, int ldc,
            int N, int K, int M, int do_relu)
{
    const int BM = 64, BN = 64, BK = 32;
    __shared__ float As[BM][BK + 1];   // [m][k], pad kills STS/LDS conflicts
    __shared__ float Ws[BK][BN];       // [k][c]

    int tid = threadIdx.x;          // 256 threads
    int tx  = tid & 15;             // 16 col-groups of 4
    int ty  = tid >> 4;             // 16 row-groups of 4
    int rowTile = blockIdx.x * BM;
    int colTile = blockIdx.y * BN;
    bool wfull = (colTile + BN) <= M;

    float acc[4][4];
    #pragma unroll
    for (int i = 0; i < 4; i++)
        #pragma unroll
        for (int jj = 0; jj < 4; jj++) acc[i][jj] = 0.f;

    for (int k0 = 0; k0 < K; k0 += BK) {
        // Load A tile: coalesced float4, transposed into padded [m][k]
        #pragma unroll
        for (int pass = 0; pass < 2; pass++) {
            int m  = (tid >> 3) + pass * 32;
            int kk = (tid & 7) * 4;
            int r  = rowTile + m;
            float4 v = make_float4(0.f, 0.f, 0.f, 0.f);
            if (r < N) v = *(const float4*)(A + (size_t)r * lda + k0 + kk);
            As[m][kk + 0] = v.x; As[m][kk + 1] = v.y;
            As[m][kk + 2] = v.z; As[m][kk + 3] = v.w;
        }
        // Load W tile
        #pragma unroll
        for (int pass = 0; pass < 2; pass++) {
            int kk = (tid >> 4) + pass * 16;
            int c  = (tid & 15) * 4;
            int gc = colTile + c;
            const float* wp = W + (size_t)(k0 + kk) * ldw + gc;
            if (wfull) {
                *(float4*)&Ws[kk][c] = *(const float4*)wp;
            } else {
                #pragma unroll
                for (int q = 0; q < 4; q++)
                    Ws[kk][c + q] = (gc + q < M) ? wp[q] : 0.f;
            }
        }
        __syncthreads();

        #pragma unroll
        for (int k = 0; k < BK; k++) {
            float a0 = As[ty * 4 + 0][k];
            float a1 = As[ty * 4 + 1][k];
            float a2 = As[ty * 4 + 2][k];
            float a3 = As[ty * 4 + 3][k];
            float4 w = *(const float4*)&Ws[k][tx * 4];
            acc[0][0] += a0 * w.x; acc[0][1] += a0 * w.y; acc[0][2] += a0 * w.z; acc[0][3] += a0 * w.w;
            acc[1][0] += a1 * w.x; acc[1][1] += a1 * w.y; acc[1][2] += a1 * w.z; acc[1][3] += a1 * w.w;
            acc[2][0] += a2 * w.x; acc[2][1] += a2 * w.y; acc[2][2] += a2 * w.z; acc[2][3] += a2 * w.w;
            acc[3][0] += a3 * w.x; acc[3][1] += a3 * w.y; acc[3][2] += a3 * w.z; acc[3][3] += a3 * w.w;
        }
        __syncthreads();
    }

    #pragma unroll
    for (int i = 0; i < 4; i++) {
        int r = rowTile + ty * 4 + i;
        if (r >= N) continue;
        #pragma unroll
        for (int jj = 0; jj < 4; jj++) {
            int c = colTile + tx * 4 + jj;
            if (c >= M) continue;
            float v = acc[i][jj] + bias[c];
            if (do_relu) v = fmaxf(v, 0.f);
            C[(size_t)r * ldc + c] = v;
        }
    }
}

// ---------------- launch ------------------------------------------------
extern "C" void kernel_launch(void* const* d_in, const int* in_sizes, int n_in,
                              void* d_out, int out_size) {
    const float* x      = (const float*)d_in[0];
    const int*   ei     = (const int*)  d_in[1];
    const float* selfk  = (const float*)d_in[2];
    const float* nbrk   = (const float*)d_in[3];
    const float* biases = (const float*)d_in[4];
    const float* w1     = (const float*)d_in[5];
    const float* b1     = (const float*)d_in[6];
    const float* w2     = (const float*)d_in[7];
    const float* b2     = (const float*)d_in[8];
    float* out = (float*)d_out;

    int n = in_sizes[0] / DF;
    int E = in_sizes[1] / 2;

    float *hA, *hB, *nbr, *hidden;
    cudaGetSymbolAddress((void**)&hA, g_hA);
    cudaGetSymbolAddress((void**)&hB, g_hB);
    cudaGetSymbolAddress((void**)&nbr, g_nbr);
    cudaGetSymbolAddress((void**)&hidden, g_hidden);

    // CSR build (graph fixed across layers)
    k_zero_deg<<<(n + 255) / 256, 256>>>(n);
    k_hist<<<(E + 255) / 256, 256>>>(ei, E);
    k_scan<<<1, 1024>>>(n);
    k_scatter<<<(E + 255) / 256, 256>>>(ei, E);

    int aggBlocks = (n * 32 + 255) / 256;
    dim3 g64((n + 63) / 64, 1);

    const float* hcur = x;
    float* bufs[2] = { hA, hB };
    for (int i = 0; i < 3; i++) {
        k_agg<<<aggBlocks, 256>>>(hcur, nbr, n);
        float* hnext = bufs[i & 1];
        // self half:  cols [0,64)
        k_gemm<<<g64, 256>>>(hcur, DF, selfk + (size_t)i * DF * 64, 64,
                             biases + (size_t)i * DF, hnext, DF,
                             n, DF, 64, 1);
        // neighbor half: cols [64,128)
        k_gemm<<<g64, 256>>>(nbr, DF, nbrk + (size_t)i * DF * 64, 64,
                             biases + (size_t)i * DF + 64, hnext + 64, DF,
                             n, DF, 64, 1);
        hcur = hnext;
    }

    // MLP head
    dim3 gh((n + 63) / 64, (HID + 63) / 64);
    k_gemm<<<gh, 256>>>(hcur, DF, w1, HID, b1, hidden, HID, n, DF, HID, 1);
    dim3 go((n + 63) / 64, 1);
    k_gemm<<<go, 256>>>(hidden, HID, w2, 40, b2, out, 40, n, HID, 40, 0);
}

// round 14
// speedup vs baseline: 1.0029x; 1.0029x over previous
#include <cuda_runtime.h>
#include <cuda_bf16.h>
#include <cstdint>

// Problem constants (asserted implicitly by scratch sizing)
#define MAX_N 50000
#define MAX_E 800000
#define DF    128   // feature dim / layer width
#define HID   256   // MLP hidden

// ---------------- device scratch (static __device__, no allocs) ----------
__device__ int   g_deg[MAX_N];
__device__ int   g_row_ptr[MAX_N + 1];
__device__ int   g_cursor[MAX_N];
__device__ float g_inv_deg[MAX_N];
__device__ int   g_cols[MAX_E];

__device__ float g_hA[(size_t)MAX_N * DF];
__device__ float g_hB[(size_t)MAX_N * DF];
__device__ float g_nbr[(size_t)MAX_N * DF];
__device__ float g_hidden[(size_t)MAX_N * HID];

// ---------------- CSR build --------------------------------------------
__global__ void k_zero_deg(int n) {
    int i = blockIdx.x * blockDim.x + threadIdx.x;
    if (i < n) g_deg[i] = 0;
}

__global__ void k_hist(const int* __restrict__ ei, int E) {
    int e = blockIdx.x * blockDim.x + threadIdx.x;
    if (e < E) atomicAdd(&g_deg[ei[e]], 1);
}

// single-block exclusive scan over g_deg -> g_row_ptr / g_cursor / g_inv_deg
__global__ void k_scan(int n) {
    __shared__ int sdata[1024];
    __shared__ int s_off;
    if (threadIdx.x == 0) s_off = 0;
    __syncthreads();
    for (int base = 0; base < n; base += 1024) {
        int i = base + (int)threadIdx.x;
        int v = (i < n) ? g_deg[i] : 0;
        sdata[threadIdx.x] = v;
        __syncthreads();
        #pragma unroll
        for (int ofs = 1; ofs < 1024; ofs <<= 1) {
            int t = 0;
            if ((int)threadIdx.x >= ofs) t = sdata[threadIdx.x - ofs];
            __syncthreads();
            sdata[threadIdx.x] += t;
            __syncthreads();
        }
        int excl = s_off + sdata[threadIdx.x] - v;
        if (i < n) {
            g_row_ptr[i] = excl;
            g_cursor[i]  = excl;
            g_inv_deg[i] = 1.0f / fmaxf((float)v, 1.0f);
        }
        __syncthreads();
        if (threadIdx.x == 0) s_off += sdata[1023];
        __syncthreads();
    }
    if (threadIdx.x == 0) g_row_ptr[n] = s_off;
}

__global__ void k_scatter(const int* __restrict__ ei, int E) {
    int e = blockIdx.x * blockDim.x + threadIdx.x;
    if (e < E) {
        int r = ei[e];
        int c = ei[E + e];
        int pos = atomicAdd(&g_cursor[r], 1);
        g_cols[pos] = c;
    }
}

// ---------------- mean-neighbor aggregation (warp per node) -------------
__global__ void k_agg(const float* __restrict__ h, float* __restrict__ outp, int n) {
    int warp = (blockIdx.x * blockDim.x + threadIdx.x) >> 5;
    int lane = threadIdx.x & 31;
    if (warp >= n) return;
    int s = g_row_ptr[warp];
    int e = g_row_ptr[warp + 1];

    float4 acc0 = make_float4(0.f, 0.f, 0.f, 0.f);
    float4 acc1 = make_float4(0.f, 0.f, 0.f, 0.f);
    int j = s;
    for (; j + 1 < e; j += 2) {
        int c0 = g_cols[j];
        int c1 = g_cols[j + 1];
        float4 v0 = ((const float4*)(h + (size_t)c0 * DF))[lane];
        float4 v1 = ((const float4*)(h + (size_t)c1 * DF))[lane];
        acc0.x += v0.x; acc0.y += v0.y; acc0.z += v0.z; acc0.w += v0.w;
        acc1.x += v1.x; acc1.y += v1.y; acc1.z += v1.z; acc1.w += v1.w;
    }
    if (j < e) {
        int c0 = g_cols[j];
        float4 v0 = ((const float4*)(h + (size_t)c0 * DF))[lane];
        acc0.x += v0.x; acc0.y += v0.y; acc0.z += v0.z; acc0.w += v0.w;
    }
    float sc = g_inv_deg[warp];
    float4 r;
    r.x = (acc0.x + acc1.x) * sc;
    r.y = (acc0.y + acc1.y) * sc;
    r.z = (acc0.z + acc1.z) * sc;
    r.w = (acc0.w + acc1.w) * sc;
    ((float4*)(outp + (size_t)warp * DF))[lane] = r;
}

// ---------------- tiled fp32 GEMM: C = [relu](A @ W + bias) -------------
// A: [N,K] lda; W: [K,M] ldw; C: [N,*] ldc (caller pre-offsets C/bias cols)
__global__ __launch_bounds__(256, 4)
void k_gemm(const float* __restrict__ A, int lda,
            const float* __restrict__ W, int ldw,
            const float* __restrict__ bias,
            float* __restrict__ C, int ldc,
            int N, int K, int M, int do_relu)
{
    const int BM = 64, BN = 64, BK = 32;
    __shared__ float As[BM][BK + 1];   // [m][k], pad kills STS/LDS conflicts
    __shared__ float Ws[BK][BN];       // [k][c]

    int tid = threadIdx.x;          // 256 threads
    int tx  = tid & 15;             // 16 col-groups of 4
    int ty  = tid >> 4;             // 16 row-groups of 4
    int rowTile = blockIdx.x * BM;
    int colTile = blockIdx.y * BN;
    bool wfull = (colTile + BN) <= M;

    float acc[4][4];
    #pragma unroll
    for (int i = 0; i < 4; i++)
        #pragma unroll
        for (int jj = 0; jj < 4; jj++) acc[i][jj] = 0.f;

    for (int k0 = 0; k0 < K; k0 += BK) {
        // Load A tile: coalesced float4, transposed into padded [m][k]
        #pragma unroll
        for (int pass = 0; pass < 2; pass++) {
            int m  = (tid >> 3) + pass * 32;
            int kk = (tid & 7) * 4;
            int r  = rowTile + m;
            float4 v = make_float4(0.f, 0.f, 0.f, 0.f);
            if (r < N) v = *(const float4*)(A + (size_t)r * lda + k0 + kk);
            As[m][kk + 0] = v.x; As[m][kk + 1] = v.y;
            As[m][kk + 2] = v.z; As[m][kk + 3] = v.w;
        }
        // Load W tile
        #pragma unroll
        for (int pass = 0; pass < 2; pass++) {
            int kk = (tid >> 4) + pass * 16;
            int c  = (tid & 15) * 4;
            int gc = colTile + c;
            const float* wp = W + (size_t)(k0 + kk) * ldw + gc;
            if (wfull) {
                *(float4*)&Ws[kk][c] = *(const float4*)wp;
            } else {
                #pragma unroll
                for (int q = 0; q < 4; q++)
                    Ws[kk][c + q] = (gc + q < M) ? wp[q] : 0.f;
            }
        }
        __syncthreads();

        #pragma unroll
        for (int k = 0; k < BK; k++) {
            float a0 = As[ty * 4 + 0][k];
            float a1 = As[ty * 4 + 1][k];
            float a2 = As[ty * 4 + 2][k];
            float a3 = As[ty * 4 + 3][k];
            float4 w = *(const float4*)&Ws[k][tx * 4];
            acc[0][0] += a0 * w.x; acc[0][1] += a0 * w.y; acc[0][2] += a0 * w.z; acc[0][3] += a0 * w.w;
            acc[1][0] += a1 * w.x; acc[1][1] += a1 * w.y; acc[1][2] += a1 * w.z; acc[1][3] += a1 * w.w;
            acc[2][0] += a2 * w.x; acc[2][1] += a2 * w.y; acc[2][2] += a2 * w.z; acc[2][3] += a2 * w.w;
            acc[3][0] += a3 * w.x; acc[3][1] += a3 * w.y; acc[3][2] += a3 * w.z; acc[3][3] += a3 * w.w;
        }
        __syncthreads();
    }

    #pragma unroll
    for (int i = 0; i < 4; i++) {
        int r = rowTile + ty * 4 + i;
        if (r >= N) continue;
        #pragma unroll
        for (int jj = 0; jj < 4; jj++) {
            int c = colTile + tx * 4 + jj;
            if (c >= M) continue;
            float v = acc[i][jj] + bias[c];
            if (do_relu) v = fmaxf(v, 0.f);
            C[(size_t)r * ldc + c] = v;
        }
    }
}

// ---------------- launch ------------------------------------------------
extern "C" void kernel_launch(void* const* d_in, const int* in_sizes, int n_in,
                              void* d_out, int out_size) {
    const float* x      = (const float*)d_in[0];
    const int*   ei     = (const int*)  d_in[1];
    const float* selfk  = (const float*)d_in[2];
    const float* nbrk   = (const float*)d_in[3];
    const float* biases = (const float*)d_in[4];
    const float* w1     = (const float*)d_in[5];
    const float* b1     = (const float*)d_in[6];
    const float* w2     = (const float*)d_in[7];
    const float* b2     = (const float*)d_in[8];
    float* out = (float*)d_out;

    int n = in_sizes[0] / DF;
    int E = in_sizes[1] / 2;

    float *hA, *hB, *nbr, *hidden;
    cudaGetSymbolAddress((void**)&hA, g_hA);
    cudaGetSymbolAddress((void**)&hB, g_hB);
    cudaGetSymbolAddress((void**)&nbr, g_nbr);
    cudaGetSymbolAddress((void**)&hidden, g_hidden);

    // CSR build (graph fixed across layers)
    k_zero_deg<<<(n + 255) / 256, 256>>>(n);
    k_hist<<<(E + 255) / 256, 256>>>(ei, E);
    k_scan<<<1, 1024>>>(n);
    k_scatter<<<(E + 255) / 256, 256>>>(ei, E);

    int aggBlocks = (n * 32 + 255) / 256;
    dim3 g64((n + 63) / 64, 1);

    const float* hcur = x;
    float* bufs[2] = { hA, hB };
    for (int i = 0; i < 3; i++) {
        k_agg<<<aggBlocks, 256>>>(hcur, nbr, n);
        float* hnext = bufs[i & 1];
        // self half:  cols [0,64)
        k_gemm<<<g64, 256>>>(hcur, DF, selfk + (size_t)i * DF * 64, 64,
                             biases + (size_t)i * DF, hnext, DF,
                             n, DF, 64, 1);
        // neighbor half: cols [64,128)
        k_gemm<<<g64, 256>>>(nbr, DF, nbrk + (size_t)i * DF * 64, 64,
                             biases + (size_t)i * DF + 64, hnext + 64, DF,
                             n, DF, 64, 1);
        hcur = hnext;
    }

    // MLP head
    dim3 gh((n + 63) / 64, (HID + 63) / 64);
    k_gemm<<<gh, 256>>>(hcur, DF, w1, HID, b1, hidden, HID, n, DF, HID, 1);
    dim3 go((n + 63) / 64, 1);
    k_gemm<<<go, 256>>>(hidden, HID, w2, 40, b2, out, 40, n, HID, 40, 0);
}

// round 15
// speedup vs baseline: 1.0060x; 1.0031x over previous
#include <cuda_runtime.h>
#include <cuda_bf16.h>
#include <cstdint>

// Problem constants (asserted implicitly by scratch sizing)
#define MAX_N 50000
#define MAX_E 800000
#define DF    128   // feature dim / layer width
#define HID   256   // MLP hidden

// ---------------- device scratch (static __device__, no allocs) ----------
__device__ int   g_deg[MAX_N];
__device__ int   g_row_ptr[MAX_N + 1];
__device__ int   g_cursor[MAX_N];
__device__ float g_inv_deg[MAX_N];
__device__ int   g_cols[MAX_E];

__device__ float g_hA[(size_t)MAX_N * DF];
__device__ float g_hB[(size_t)MAX_N * DF];
__device__ float g_nbr[(size_t)MAX_N * DF];
__device__ float g_hidden[(size_t)MAX_N * HID];

// ---------------- CSR build --------------------------------------------
__global__ void k_zero_deg(int n) {
    int i = blockIdx.x * blockDim.x + threadIdx.x;
    if (i < n) g_deg[i] = 0;
}

__global__ void k_hist(const int* __restrict__ ei, int E) {
    int e = blockIdx.x * blockDim.x + threadIdx.x;
    if (e < E) atomicAdd(&g_deg[ei[e]], 1);
}

// single-block exclusive scan over g_deg -> g_row_ptr / g_cursor / g_inv_deg
__global__ void k_scan(int n) {
    __shared__ int sdata[1024];
    __shared__ int s_off;
    if (threadIdx.x == 0) s_off = 0;
    __syncthreads();
    for (int base = 0; base < n; base += 1024) {
        int i = base + (int)threadIdx.x;
        int v = (i < n) ? g_deg[i] : 0;
        sdata[threadIdx.x] = v;
        __syncthreads();
        #pragma unroll
        for (int ofs = 1; ofs < 1024; ofs <<= 1) {
            int t = 0;
            if ((int)threadIdx.x >= ofs) t = sdata[threadIdx.x - ofs];
            __syncthreads();
            sdata[threadIdx.x] += t;
            __syncthreads();
        }
        int excl = s_off + sdata[threadIdx.x] - v;
        if (i < n) {
            g_row_ptr[i] = excl;
            g_cursor[i]  = excl;
            g_inv_deg[i] = 1.0f / fmaxf((float)v, 1.0f);
        }
        __syncthreads();
        if (threadIdx.x == 0) s_off += sdata[1023];
        __syncthreads();
    }
    if (threadIdx.x == 0) g_row_ptr[n] = s_off;
}

__global__ void k_scatter(const int* __restrict__ ei, int E) {
    int e = blockIdx.x * blockDim.x + threadIdx.x;
    if (e < E) {
        int r = ei[e];
        int c = ei[E + e];
        int pos = atomicAdd(&g_cursor[r], 1);
        g_cols[pos] = c;
    }
}

// ---------------- mean-neighbor aggregation (warp per node) -------------
__global__ void k_agg(const float* __restrict__ h, float* __restrict__ outp, int n) {
    int warp = (blockIdx.x * blockDim.x + threadIdx.x) >> 5;
    int lane = threadIdx.x & 31;
    if (warp >= n) return;
    int s = g_row_ptr[warp];
    int e = g_row_ptr[warp + 1];

    float4 acc0 = make_float4(0.f, 0.f, 0.f, 0.f);
    float4 acc1 = make_float4(0.f, 0.f, 0.f, 0.f);
    int j = s;
    for (; j + 1 < e; j += 2) {
        int c0 = g_cols[j];
        int c1 = g_cols[j + 1];
        float4 v0 = ((const float4*)(h + (size_t)c0 * DF))[lane];
        float4 v1 = ((const float4*)(h + (size_t)c1 * DF))[lane];
        acc0.x += v0.x; acc0.y += v0.y; acc0.z += v0.z; acc0.w += v0.w;
        acc1.x += v1.x; acc1.y += v1.y; acc1.z += v1.z; acc1.w += v1.w;
    }
    if (j < e) {
        int c0 = g_cols[j];
        float4 v0 = ((const float4*)(h + (size_t)c0 * DF))[lane];
        acc0.x += v0.x; acc0.y += v0.y; acc0.z += v0.z; acc0.w += v0.w;
    }
    float sc = g_inv_deg[warp];
    float4 r;
    r.x = (acc0.x + acc1.x) * sc;
    r.y = (acc0.y + acc1.y) * sc;
    r.z = (acc0.z + acc1.z) * sc;
    r.w = (acc0.w + acc1.w) * sc;
    ((float4*)(outp + (size_t)warp * DF))[lane] = r;
}

// ---------------- tiled fp32 GEMM: C = [relu](A @ W + bias) -------------
// A: [N,K] lda; W: [K,M] ldw; C: [N,*] ldc (caller pre-offsets C/bias cols)
__global__ __launch_bounds__(256, 4)
void k_gemm(const float* __restrict__ A, int lda,
            const float* __restrict__ W, int ldw,
            const float* __restrict__ bias,
            float* __restrict__ C, int ldc,
            int N, int K, int M, int do_relu)
{
    const int BM = 64, BN = 64, BK = 32;
    __shared__ float As[BM][BK + 1];   // [m][k], pad kills STS/LDS conflicts
    __shared__ float Ws[BK][BN];       // [k][c]

    int tid = threadIdx.x;          // 256 threads
    int tx  = tid & 15;             // 16 col-groups of 4
    int ty  = tid >> 4;             // 16 row-groups of 4
    int rowTile = blockIdx.x * BM;
    int colTile = blockIdx.y * BN;
    bool wfull = (colTile + BN) <= M;

    float acc[4][4];
    #pragma unroll
    for (int i = 0; i < 4; i++)
        #pragma unroll
        for (int jj = 0; jj < 4; jj++) acc[i][jj] = 0.f;

    for (int k0 = 0; k0 < K; k0 += BK) {
        // Load A tile: coalesced float4, transposed into padded [m][k]
        #pragma unroll
        for (int pass = 0; pass < 2; pass++) {
            int m  = (tid >> 3) + pass * 32;
            int kk = (tid & 7) * 4;
            int r  = rowTile + m;
            float4 v = make_float4(0.f, 0.f, 0.f, 0.f);
            if (r < N) v = *(const float4*)(A + (size_t)r * lda + k0 + kk);
            As[m][kk + 0] = v.x; As[m][kk + 1] = v.y;
            As[m][kk + 2] = v.z; As[m][kk + 3] = v.w;
        }
        // Load W tile
        #pragma unroll
        for (int pass = 0; pass < 2; pass++) {
            int kk = (tid >> 4) + pass * 16;
            int c  = (tid & 15) * 4;
            int gc = colTile + c;
            const float* wp = W + (size_t)(k0 + kk) * ldw + gc;
            if (wfull) {
                *(float4*)&Ws[kk][c] = *(const float4*)wp;
            } else {
                #pragma unroll
                for (int q = 0; q < 4; q++)
                    Ws[kk][c + q] = (gc + q < M) ? wp[q] : 0.f;
            }
        }
        __syncthreads();

        #pragma unroll
        for (int k = 0; k < BK; k++) {
            float a0 = As[ty * 4 + 0][k];
            float a1 = As[ty * 4 + 1][k];
            float a2 = As[ty * 4 + 2][k];
            float a3 = As[ty * 4 + 3][k];
            float4 w = *(const float4*)&Ws[k][tx * 4];
            acc[0][0] += a0 * w.x; acc[0][1] += a0 * w.y; acc[0][2] += a0 * w.z; acc[0][3] += a0 * w.w;
            acc[1][0] += a1 * w.x; acc[1][1] += a1 * w.y; acc[1][2] += a1 * w.z; acc[1][3] += a1 * w.w;
            acc[2][0] += a2 * w.x; acc[2][1] += a2 * w.y; acc[2][2] += a2 * w.z; acc[2][3] += a2 * w.w;
            acc[3][0] += a3 * w.x; acc[3][1] += a3 * w.y; acc[3][2] += a3 * w.z; acc[3][3] += a3 * w.w;
        }
        __syncthreads();
    }

    #pragma unroll
    for (int i = 0; i < 4; i++) {
        int r = rowTile + ty * 4 + i;
        if (r >= N) continue;
        #pragma unroll
        for (int jj = 0; jj < 4; jj++) {
            int c = colTile + tx * 4 + jj;
            if (c >= M) continue;
            float v = acc[i][jj] + bias[c];
            if (do_relu) v = fmaxf(v, 0.f);
            C[(size_t)r * ldc + c] = v;
        }
    }
}

// ---------------- launch ------------------------------------------------
extern "C" void kernel_launch(void* const* d_in, const int* in_sizes, int n_in,
                              void* d_out, int out_size) {
    const float* x      = (const float*)d_in[0];
    const int*   ei     = (const int*)  d_in[1];
    const float* selfk  = (const float*)d_in[2];
    const float* nbrk   = (const float*)d_in[3];
    const float* biases = (const float*)d_in[4];
    const float* w1     = (const float*)d_in[5];
    const float* b1     = (const float*)d_in[6];
    const float* w2     = (const float*)d_in[7];
    const float* b2     = (const float*)d_in[8];
    float* out = (float*)d_out;

    int n = in_sizes[0] / DF;
    int E = in_sizes[1] / 2;

    float *hA, *hB, *nbr, *hidden;
    cudaGetSymbolAddress((void**)&hA, g_hA);
    cudaGetSymbolAddress((void**)&hB, g_hB);
    cudaGetSymbolAddress((void**)&nbr, g_nbr);
    cudaGetSymbolAddress((void**)&hidden, g_hidden);

    // CSR build (graph fixed across layers)
    k_zero_deg<<<(n + 255) / 256, 256>>>(n);
    k_hist<<<(E + 255) / 256, 256>>>(ei, E);
    k_scan<<<1, 1024>>>(n);
    k_scatter<<<(E + 255) / 256, 256>>>(ei, E);

    int aggBlocks = (n * 32 + 255) / 256;
    dim3 g64((n + 63) / 64, 1);

    const float* hcur = x;
    float* bufs[2] = { hA, hB };
    for (int i = 0; i < 3; i++) {
        k_agg<<<aggBlocks, 256>>>(hcur, nbr, n);
        float* hnext = bufs[i & 1];
        // self half:  cols [0,64)
        k_gemm<<<g64, 256>>>(hcur, DF, selfk + (size_t)i * DF * 64, 64,
                             biases + (size_t)i * DF, hnext, DF,
                             n, DF, 64, 1);
        // neighbor half: cols [64,128)
        k_gemm<<<g64, 256>>>(nbr, DF, nbrk + (size_t)i * DF * 64, 64,
                             biases + (size_t)i * DF + 64, hnext + 64, DF,
                             n, DF, 64, 1);
        hcur = hnext;
    }

    // MLP head
    dim3 gh((n + 63) / 64, (HID + 63) / 64);
    k_gemm<<<gh, 256>>>(hcur, DF, w1, HID, b1, hidden, HID, n, DF, HID, 1);
    dim3 go((n + 63) / 64, 1);
    k_gemm<<<go, 256>>>(hidden, HID, w2, 40, b2, out, 40, n, HID, 40, 0);
}